// round 11
// baseline (speedup 1.0000x reference)
#include <cuda_runtime.h>
#include <math.h>

// Problem constants
#define NUM_R 8
#define KLEN  128
#define HID   32
#define LREC  4096
#define KP1   (KLEN + 1)
#define MAXB1 16
#define NT    4               // tiles per warp (4 samples each) = 16 samples/warp

// Fast-path folded table: contribution of receiver r, batch b1:
//   S = c.x + u * c.y   (vy baked in)
__device__ float2 g_C[MAXB1][NUM_R][KP1][HID];
// Raw prefix tables (PA, PB) for the general fallback path
__device__ float  g_P[NUM_R][KP1][2][HID];
// vy[b1][r] for the fallback path
__device__ float  g_vy[MAXB1][NUM_R];

// Table build: one block per (b1, r). Blocks with equal r write identical
// values to g_P (benign identical-value race).
__global__ void __launch_bounds__(256) prep_kernel(
    const float* __restrict__ W1, const float* __restrict__ rec)
{
    __shared__ float sTA[8][HID];
    __shared__ float sTB[8][HID];
    int r   = blockIdx.x & (NUM_R - 1);
    int b1  = blockIdx.x >> 3;
    int h   = threadIdx.x & 31;
    int seg = threadIdx.x >> 5;   // 0..7, 16 k's each
    const float inv = 1.0f / 16384.0f;

    int k0 = seg * 16;
    float a = 0.f, b = 0.f;
    if (seg == 0) { g_P[r][0][0][h] = 0.f; g_P[r][0][1][h] = 0.f; }
#pragma unroll
    for (int j = 0; j < 16; ++j) {
        int k = k0 + j;
        float w = W1[(r * KLEN + k) * HID + h];
        a += w;
        b += (float)k * w;
        g_P[r][k + 1][0][h] = a;
        g_P[r][k + 1][1][h] = b;
    }
    sTA[seg][h] = a;
    sTB[seg][h] = b;
    __syncthreads();

    float offA = 0.f, offB = 0.f;
    for (int s = 0; s < seg; ++s) { offA += sTA[s][h]; offB += sTB[s][h]; }
    if (seg > 0) {
#pragma unroll
        for (int j = 0; j < 16; ++j) {
            int k = k0 + j;
            g_P[r][k + 1][0][h] += offA;
            g_P[r][k + 1][1][h] += offB;
        }
    }
    __syncthreads();

    const float* rr = rec + (size_t)(b1 * NUM_R + r) * LREC;
    float vy = 0.5f * rr[2047] + 0.5f * rr[2048];
    if (threadIdx.x == 0) g_vy[b1][r] = vy;

    const float inv2 = 2.0f / 16384.0f;
    float Aend = g_P[r][KLEN][0][h];
    float Bend = g_P[r][KLEN][1][h];
    float Base = fmaf(-inv, Bend, Aend);
    for (int k = seg; k < KP1; k += 8) {
        float pa = g_P[r][k][0][h], pb = g_P[r][k][1][h];
        float2 c;
        c.x = vy * fmaf(inv2, pb, Base);
        c.y = vy * fmaf(2.0f, pa, -Aend);
        g_C[b1][r][k][h] = c;
    }
    // Signal PDL dependents (tof) that our global stores are ready.
    asm volatile("griddepcontrol.launch_dependents;" ::: "memory");
}

// Warp-autonomous main kernel: each warp owns 16 samples = 4 tiles of 4.
// Lane layout per tile: s_loc = lane>>3 (0..3), r = lane&7.
// No block-wide barriers; smem ordered by __syncwarp only.
__global__ void __launch_bounds__(256) tof_kernel(
    const float* __restrict__ sloc,   // (B1*B2, 3)
    const float* __restrict__ emit,   // (3,)
    const float* __restrict__ rloc,   // (R, 3)
    const float* __restrict__ b1v,    // (HID,)
    const float* __restrict__ W2,     // (HID,)
    const float* __restrict__ b2v,    // (1,)
    float* __restrict__ out,          // (B1*B2,)
    int total, int b2n, int b1shift)
{
    __shared__ __align__(16) float2 sg[8][NT][4][NUM_R];

    int tid  = threadIdx.x;
    int wid  = tid >> 5;
    int lane = tid & 31;
    int s_loc = lane >> 3;
    int r     = lane & 7;
    int s_base = ((int)blockIdx.x * 8 + wid) * (4 * NT);
    const float inv = 1.0f / 16384.0f;
    const float SCALE = 96000.0f / 343.0f;

    // ---- Phase 1: issue ALL coordinate loads first (max MLP) ----
    float cx[NT], cy[NT], cz[NT];
    bool  vv[NT];
#pragma unroll
    for (int t = 0; t < NT; ++t) {
        int s = s_base + t * 4 + s_loc;
        vv[t] = s < total;
        cx[t] = 0.f; cy[t] = 0.f; cz[t] = 0.f;
        if (vv[t]) {
            const float* p = sloc + (size_t)s * 3;
            cx[t] = p[0]; cy[t] = p[1]; cz[t] = p[2];
        }
    }
    float ex = emit[0], ey = emit[1], ez = emit[2];
    const float* rp = rloc + r * 3;
    float rx = rp[0], ry = rp[1], rz = rp[2];
    // uniform epilogue params (hoisted to overlap with geometry)
    float blane = b1v[lane];
    float wlane = W2[lane];
    float b2s   = b2v[0];

    // ---- geometry per tile ----
    bool ok = true;
#pragma unroll
    for (int t = 0; t < NT; ++t) {
        int offv = 0; float uv = 0.f;
        if (vv[t]) {
            int s = s_base + t * 4 + s_loc;
            float dx = cx[t] - ex, dy = cy[t] - ey, dz = cz[t] - ez;
            float de = sqrtf(dx * dx + dy * dy + dz * dz);
            float qx = cx[t] - rx, qy = cy[t] - ry, qz = cz[t] - rz;
            float dr = sqrtf(qx * qx + qy * qy + qz * qz);
            int cs = (int)rintf((de + dr) * SCALE) - (KLEN / 2);
            int m0 = 4 * cs - 8192;
            int kb = max(min(-m0, KLEN), 0);
            ok = ok && (m0 >= -16384) && (m0 <= 16384 - KLEN);
            int b1 = (b1shift >= 0) ? (s >> b1shift)
                                    : (int)((unsigned)s / (unsigned)b2n);
            offv = ((b1 * NUM_R + r) * KP1 + kb) * (HID * 8);
            uv = (float)m0 * inv;
        }
        sg[wid][t][s_loc][r] = make_float2(__int_as_float(offv), uv);
    }
    bool fast = __all_sync(0xffffffffu, ok);
    __syncwarp();
    // Wait for prep's tables (PDL). No-op when launched without PDL.
    asm volatile("griddepcontrol.wait;" ::: "memory");

    // ---- Phase 2 + epilogue, per tile ----
    const char* basep = (const char*)(&g_C[0][0][0][0]) + lane * 8;

#pragma unroll
    for (int t = 0; t < NT; ++t) {
        int s0g = s_base + t * 4;
        float acc0 = 0.f, acc1 = 0.f, acc2 = 0.f, acc3 = 0.f;

        if (fast) {
            const float4* row0 = (const float4*)&sg[wid][t][0][0];
            const float4* row1 = (const float4*)&sg[wid][t][1][0];
            const float4* row2 = (const float4*)&sg[wid][t][2][0];
            const float4* row3 = (const float4*)&sg[wid][t][3][0];
#pragma unroll
            for (int r2 = 0; r2 < 4; ++r2) {   // two receivers per iter
                float4 a = row0[r2], b = row1[r2], c = row2[r2], d = row3[r2];
                float2 ca0 = *(const float2*)(basep + __float_as_int(a.x));
                float2 cb0 = *(const float2*)(basep + __float_as_int(b.x));
                float2 cc0 = *(const float2*)(basep + __float_as_int(c.x));
                float2 cd0 = *(const float2*)(basep + __float_as_int(d.x));
                float2 ca1 = *(const float2*)(basep + __float_as_int(a.z));
                float2 cb1 = *(const float2*)(basep + __float_as_int(b.z));
                float2 cc1 = *(const float2*)(basep + __float_as_int(c.z));
                float2 cd1 = *(const float2*)(basep + __float_as_int(d.z));
                acc0 = fmaf(a.y, ca0.y, acc0 + ca0.x);
                acc1 = fmaf(b.y, cb0.y, acc1 + cb0.x);
                acc2 = fmaf(c.y, cc0.y, acc2 + cc0.x);
                acc3 = fmaf(d.y, cd0.y, acc3 + cd0.x);
                acc0 = fmaf(a.w, ca1.y, acc0 + ca1.x);
                acc1 = fmaf(b.w, cb1.y, acc1 + cb1.x);
                acc2 = fmaf(c.w, cc1.y, acc2 + cc1.x);
                acc3 = fmaf(d.w, cd1.y, acc3 + cd1.x);
            }
        } else {
            // General fallback (rare): reconstruct m0 exactly from u.
            float accs[4];
            for (int j = 0; j < 4; ++j) {
                accs[j] = 0.f;
                int sample = s0g + j;
                if (sample >= total) continue;
                int b1 = (b1shift >= 0) ? (sample >> b1shift)
                                        : (int)((unsigned)sample / (unsigned)b2n);
                float a = 0.f;
                for (int rr = 0; rr < NUM_R; ++rr) {
                    float2 g = sg[wid][t][j][rr];
                    int m0 = __float2int_rn(g.y * 16384.0f);
                    float vy = g_vy[b1][rr];
                    int ka = max(min(-16384 - m0, KLEN), 0);
                    int kb = max(min(-m0,          KLEN), 0);
                    int kd = max(min(16384 - m0,   KLEN), 0);
                    float m0f = (float)m0;
                    if (kb > ka) {
                        float pa = g_P[rr][kb][0][lane] - g_P[rr][ka][0][lane];
                        float pb = g_P[rr][kb][1][lane] - g_P[rr][ka][1][lane];
                        a += vy * (fmaf(m0f, inv, 1.0f) * pa + inv * pb);
                    }
                    if (kd > kb) {
                        float pa = g_P[rr][kd][0][lane] - g_P[rr][kb][0][lane];
                        float pb = g_P[rr][kd][1][lane] - g_P[rr][kb][1][lane];
                        a += vy * (fmaf(-m0f, inv, 1.0f) * pa - inv * pb);
                    }
                }
                accs[j] = a;
            }
            acc0 = accs[0]; acc1 = accs[1]; acc2 = accs[2]; acc3 = accs[3];
        }

        // relu(acc + b1) * W2, merged 4-sample warp reduction (proven form:
        // all shuffles unconditional; ternaries select only lane-local sums)
        float c0 = fmaxf(acc0 + blane, 0.f) * wlane;
        float c1 = fmaxf(acc1 + blane, 0.f) * wlane;
        float c2 = fmaxf(acc2 + blane, 0.f) * wlane;
        float c3 = fmaxf(acc3 + blane, 0.f) * wlane;

        float t0 = __shfl_xor_sync(0xffffffffu, c0, 16);
        float t1 = __shfl_xor_sync(0xffffffffu, c1, 16);
        float t2 = __shfl_xor_sync(0xffffffffu, c2, 16);
        float t3 = __shfl_xor_sync(0xffffffffu, c3, 16);
        bool lo16 = lane < 16;
        float v = lo16 ? (c0 + t0) : (c1 + t1);   // lanes0-15: s0, 16-31: s1
        float w = lo16 ? (c2 + t2) : (c3 + t3);   // lanes0-15: s2, 16-31: s3
        float tv = __shfl_xor_sync(0xffffffffu, v, 8);
        float tw = __shfl_xor_sync(0xffffffffu, w, 8);
        float z = ((lane & 8) == 0) ? (v + tv) : (w + tw);
        // lanes 0-7: s0, 8-15: s2, 16-23: s1, 24-31: s3
        z += __shfl_xor_sync(0xffffffffu, z, 4);
        z += __shfl_xor_sync(0xffffffffu, z, 2);
        z += __shfl_xor_sync(0xffffffffu, z, 1);

        if ((lane & 7) == 0) {
            int g = ((lane >> 2) & 2) | (lane >> 4);   // 0->0, 8->2, 16->1, 24->3
            int idx = s0g + g;
            if (idx < total) out[idx] = z + b2s;
        }
    }
}

extern "C" void kernel_launch(void* const* d_in, const int* in_sizes, int n_in,
                              void* d_out, int out_size) {
    const float* rec  = (const float*)d_in[0];
    const float* sloc = (const float*)d_in[1];
    const float* emit = (const float*)d_in[2];
    const float* rloc = (const float*)d_in[3];
    const float* W1   = (const float*)d_in[4];
    const float* b1v  = (const float*)d_in[5];
    const float* W2   = (const float*)d_in[6];
    const float* b2v  = (const float*)d_in[7];
    float* out = (float*)d_out;

    int nb1 = in_sizes[0] / (NUM_R * LREC);       // B1
    if (nb1 < 1) nb1 = 1;
    if (nb1 > MAXB1) nb1 = MAXB1;
    int total = out_size;                         // B1*B2 samples
    int b2n = total / nb1;

    int b1shift = -1;
    if (b2n > 0 && (b2n & (b2n - 1)) == 0) {
        b1shift = 0;
        while ((1 << b1shift) != b2n) ++b1shift;
    }

    prep_kernel<<<NUM_R * nb1, 256>>>(W1, rec);

    int spb = 8 * 4 * NT;                         // samples per block (128)
    int blocks = (total + spb - 1) / spb;

    // PDL launch: tof's geometry overlaps prep; fallback to plain launch.
    cudaLaunchConfig_t cfg = {};
    cfg.gridDim  = dim3((unsigned)blocks, 1, 1);
    cfg.blockDim = dim3(256, 1, 1);
    cfg.dynamicSmemBytes = 0;
    cfg.stream = 0;
    cudaLaunchAttribute at[1];
    at[0].id = cudaLaunchAttributeProgrammaticStreamSerialization;
    at[0].val.programmaticStreamSerializationAllowed = 1;
    cfg.attrs = at;
    cfg.numAttrs = 1;
    cudaError_t e = cudaLaunchKernelEx(&cfg, tof_kernel,
                                       sloc, emit, rloc, b1v, W2, b2v, out,
                                       total, b2n, b1shift);
    if (e != cudaSuccess) {
        (void)cudaGetLastError();   // clear sticky error
        tof_kernel<<<blocks, 256>>>(sloc, emit, rloc, b1v, W2, b2v, out,
                                    total, b2n, b1shift);
    }
}

// round 12
// speedup vs baseline: 1.1577x; 1.1577x over previous
#include <cuda_runtime.h>
#include <math.h>

// Problem constants
#define NUM_R 8
#define KLEN  128
#define HID   32
#define LREC  4096
#define KP1   (KLEN + 1)
#define MAXB1 16

// Fast-path folded table: contribution of receiver r, batch b1:
//   S = c.x + u * c.y   (vy baked in)
__device__ float2 g_C[MAXB1][NUM_R][KP1][HID];
// Raw prefix tables (PA, PB) for the general fallback path
__device__ float  g_P[NUM_R][KP1][2][HID];
// vy[b1][r] for the fallback path
__device__ float  g_vy[MAXB1][NUM_R];

// Table build: one block per (b1, r). Blocks with equal r write identical
// values to g_P (benign identical-value race).
__global__ void __launch_bounds__(256) prep_kernel(
    const float* __restrict__ W1, const float* __restrict__ rec)
{
    __shared__ float sTA[8][HID];
    __shared__ float sTB[8][HID];
    int r   = blockIdx.x & (NUM_R - 1);
    int b1  = blockIdx.x >> 3;
    int h   = threadIdx.x & 31;
    int seg = threadIdx.x >> 5;   // 0..7, 16 k's each
    const float inv = 1.0f / 16384.0f;

    int k0 = seg * 16;
    float a = 0.f, b = 0.f;
    if (seg == 0) { g_P[r][0][0][h] = 0.f; g_P[r][0][1][h] = 0.f; }
#pragma unroll
    for (int j = 0; j < 16; ++j) {
        int k = k0 + j;
        float w = W1[(r * KLEN + k) * HID + h];
        a += w;
        b += (float)k * w;
        g_P[r][k + 1][0][h] = a;
        g_P[r][k + 1][1][h] = b;
    }
    sTA[seg][h] = a;
    sTB[seg][h] = b;
    __syncthreads();

    float offA = 0.f, offB = 0.f;
    for (int s = 0; s < seg; ++s) { offA += sTA[s][h]; offB += sTB[s][h]; }
    if (seg > 0) {
#pragma unroll
        for (int j = 0; j < 16; ++j) {
            int k = k0 + j;
            g_P[r][k + 1][0][h] += offA;
            g_P[r][k + 1][1][h] += offB;
        }
    }
    __syncthreads();

    const float* rr = rec + (size_t)(b1 * NUM_R + r) * LREC;
    float vy = 0.5f * rr[2047] + 0.5f * rr[2048];
    if (threadIdx.x == 0) g_vy[b1][r] = vy;

    const float inv2 = 2.0f / 16384.0f;
    float Aend = g_P[r][KLEN][0][h];
    float Bend = g_P[r][KLEN][1][h];
    float Base = fmaf(-inv, Bend, Aend);
    for (int k = seg; k < KP1; k += 8) {
        float pa = g_P[r][k][0][h], pb = g_P[r][k][1][h];
        float2 c;
        c.x = vy * fmaf(inv2, pb, Base);
        c.y = vy * fmaf(2.0f, pa, -Aend);
        g_C[b1][r][k][h] = c;
    }
    // Signal PDL dependents (tof) that our global stores are ready.
    asm volatile("griddepcontrol.launch_dependents;" ::: "memory");
}

// Warp-autonomous main kernel: each warp owns 8 samples = 2 tiles of 4.
// Fast path: base coefficients for kb==128 live in registers (warp-uniform);
// per sample only smem u's + FMA. Rare kb<128 pairs fixed via ballot loop.
__global__ void __launch_bounds__(256) tof_kernel(
    const float* __restrict__ sloc,   // (B1*B2, 3)
    const float* __restrict__ emit,   // (3,)
    const float* __restrict__ rloc,   // (R, 3)
    const float* __restrict__ b1v,    // (HID,)
    const float* __restrict__ W2,     // (HID,)
    const float* __restrict__ b2v,    // (1,)
    float* __restrict__ out,          // (B1*B2,)
    int total, int b2n, int b1shift)
{
    __shared__ __align__(16) float2 sg[8][2][4][NUM_R];

    int tid  = threadIdx.x;
    int wid  = tid >> 5;
    int lane = tid & 31;
    int s_loc = lane >> 3;
    int r     = lane & 7;
    int s_base = ((int)blockIdx.x * 8 + wid) * 8;
    const float inv = 1.0f / 16384.0f;
    const float SCALE = 96000.0f / 343.0f;

    int b1w = (b1shift >= 0) ? (s_base >> b1shift)
                             : (int)((unsigned)s_base / (unsigned)b2n);

    // ---- Phase 1: issue ALL coordinate loads first (max MLP) ----
    float cxv[2], cyv[2], czv[2];
    bool  vv[2];
#pragma unroll
    for (int t = 0; t < 2; ++t) {
        int s = s_base + t * 4 + s_loc;
        vv[t] = s < total;
        cxv[t] = 0.f; cyv[t] = 0.f; czv[t] = 0.f;
        if (vv[t]) {
            const float* p = sloc + (size_t)s * 3;
            cxv[t] = p[0]; cyv[t] = p[1]; czv[t] = p[2];
        }
    }
    float ex = emit[0], ey = emit[1], ez = emit[2];
    const float* rp = rloc + r * 3;
    float rx = rp[0], ry = rp[1], rz = rp[2];
    float blane = b1v[lane];
    float wlane = W2[lane];
    float b2s   = b2v[0];

    // ---- geometry per tile ----
    bool ok = true;
    bool corr[2];
#pragma unroll
    for (int t = 0; t < 2; ++t) {
        int offv = 0; float uv = 0.f;
        corr[t] = false;
        if (vv[t]) {
            int s = s_base + t * 4 + s_loc;
            float dx = cxv[t] - ex, dy = cyv[t] - ey, dz = czv[t] - ez;
            float de = sqrtf(dx * dx + dy * dy + dz * dz);
            float qx = cxv[t] - rx, qy = cyv[t] - ry, qz = czv[t] - rz;
            float dr = sqrtf(qx * qx + qy * qy + qz * qz);
            int cs = (int)rintf((de + dr) * SCALE) - (KLEN / 2);
            int m0 = 4 * cs - 8192;
            int kb = max(min(-m0, KLEN), 0);
            int b1 = (b1shift >= 0) ? (s >> b1shift)
                                    : (int)((unsigned)s / (unsigned)b2n);
            ok = ok && (m0 >= -16384) && (m0 <= 16384 - KLEN) && (b1 == b1w);
            corr[t] = (kb != KLEN);
            offv = ((b1 * NUM_R + r) * KP1 + kb) * (HID * 8);
            uv = (float)m0 * inv;
        }
        sg[wid][t][s_loc][r] = make_float2(__int_as_float(offv), uv);
    }
    bool fast = __all_sync(0xffffffffu, ok);
    unsigned bal0 = __ballot_sync(0xffffffffu, corr[0]);
    unsigned bal1 = __ballot_sync(0xffffffffu, corr[1]);
    __syncwarp();
    // Wait for prep's tables (PDL). No-op when launched without PDL.
    asm volatile("griddepcontrol.wait;" ::: "memory");

    const char* basep = (const char*)(&g_C[0][0][0][0]) + lane * 8;

    if (fast) {
        // ---- preload kb=128 base coefficients (warp-uniform, L1-hot) ----
        float CY0, CY1, CY2, CY3, CY4, CY5, CY6, CY7, CX = 0.f;
        {
            const float2* pb128 = (const float2*)(basep)
                + ((size_t)b1w * NUM_R * KP1 + KLEN) * 0;  // placate aliasing
            float2 t0_ = *(const float2*)(basep + (((b1w * NUM_R + 0) * KP1 + KLEN) * (HID * 8)));
            float2 t1_ = *(const float2*)(basep + (((b1w * NUM_R + 1) * KP1 + KLEN) * (HID * 8)));
            float2 t2_ = *(const float2*)(basep + (((b1w * NUM_R + 2) * KP1 + KLEN) * (HID * 8)));
            float2 t3_ = *(const float2*)(basep + (((b1w * NUM_R + 3) * KP1 + KLEN) * (HID * 8)));
            float2 t4_ = *(const float2*)(basep + (((b1w * NUM_R + 4) * KP1 + KLEN) * (HID * 8)));
            float2 t5_ = *(const float2*)(basep + (((b1w * NUM_R + 5) * KP1 + KLEN) * (HID * 8)));
            float2 t6_ = *(const float2*)(basep + (((b1w * NUM_R + 6) * KP1 + KLEN) * (HID * 8)));
            float2 t7_ = *(const float2*)(basep + (((b1w * NUM_R + 7) * KP1 + KLEN) * (HID * 8)));
            (void)pb128;
            CX = ((t0_.x + t1_.x) + (t2_.x + t3_.x)) + ((t4_.x + t5_.x) + (t6_.x + t7_.x));
            CY0 = t0_.y; CY1 = t1_.y; CY2 = t2_.y; CY3 = t3_.y;
            CY4 = t4_.y; CY5 = t5_.y; CY6 = t6_.y; CY7 = t7_.y;
        }

#pragma unroll
        for (int t = 0; t < 2; ++t) {
            int s0g = s_base + t * 4;
            float acc0 = CX, acc1 = CX, acc2 = CX, acc3 = CX;

            const float4* row0 = (const float4*)&sg[wid][t][0][0];
            const float4* row1 = (const float4*)&sg[wid][t][1][0];
            const float4* row2 = (const float4*)&sg[wid][t][2][0];
            const float4* row3 = (const float4*)&sg[wid][t][3][0];
#pragma unroll
            for (int r2 = 0; r2 < 4; ++r2) {   // receivers 2r2, 2r2+1
                float cya = (r2 == 0) ? CY0 : (r2 == 1) ? CY2 : (r2 == 2) ? CY4 : CY6;
                float cyb = (r2 == 0) ? CY1 : (r2 == 1) ? CY3 : (r2 == 2) ? CY5 : CY7;
                float4 a = row0[r2], b = row1[r2], c = row2[r2], d = row3[r2];
                acc0 = fmaf(a.y, cya, acc0); acc0 = fmaf(a.w, cyb, acc0);
                acc1 = fmaf(b.y, cya, acc1); acc1 = fmaf(b.w, cyb, acc1);
                acc2 = fmaf(c.y, cya, acc2); acc2 = fmaf(c.w, cyb, acc2);
                acc3 = fmaf(d.y, cya, acc3); acc3 = fmaf(d.w, cyb, acc3);
            }

            // ---- rare corrections: pairs with kb != 128 ----
            unsigned bal = (t == 0) ? bal0 : bal1;
            while (bal) {
                int bpos = __ffs(bal) - 1;
                bal &= bal - 1;
                int sj = bpos >> 3;
                int rr = bpos & 7;
                float2 g = sg[wid][t][sj][rr];
                float2 ck  = *(const float2*)(basep + __float_as_int(g.x));
                float2 ck1 = *(const float2*)(basep +
                              (((b1w * NUM_R + rr) * KP1 + KLEN) * (HID * 8)));
                float dlt = (ck.x - ck1.x) + g.y * (ck.y - ck1.y);
                acc0 += (sj == 0) ? dlt : 0.f;
                acc1 += (sj == 1) ? dlt : 0.f;
                acc2 += (sj == 2) ? dlt : 0.f;
                acc3 += (sj == 3) ? dlt : 0.f;
            }

            // relu + W2 dot, merged 4-sample warp reduction (proven form)
            float c0 = fmaxf(acc0 + blane, 0.f) * wlane;
            float c1 = fmaxf(acc1 + blane, 0.f) * wlane;
            float c2 = fmaxf(acc2 + blane, 0.f) * wlane;
            float c3 = fmaxf(acc3 + blane, 0.f) * wlane;

            float t0 = __shfl_xor_sync(0xffffffffu, c0, 16);
            float t1 = __shfl_xor_sync(0xffffffffu, c1, 16);
            float t2 = __shfl_xor_sync(0xffffffffu, c2, 16);
            float t3 = __shfl_xor_sync(0xffffffffu, c3, 16);
            bool lo16 = lane < 16;
            float v = lo16 ? (c0 + t0) : (c1 + t1);
            float w = lo16 ? (c2 + t2) : (c3 + t3);
            float tv = __shfl_xor_sync(0xffffffffu, v, 8);
            float tw = __shfl_xor_sync(0xffffffffu, w, 8);
            float z = ((lane & 8) == 0) ? (v + tv) : (w + tw);
            z += __shfl_xor_sync(0xffffffffu, z, 4);
            z += __shfl_xor_sync(0xffffffffu, z, 2);
            z += __shfl_xor_sync(0xffffffffu, z, 1);

            if ((lane & 7) == 0) {
                int g = ((lane >> 2) & 2) | (lane >> 4); // 0->0,8->2,16->1,24->3
                int idx = s0g + g;
                if (idx < total) out[idx] = z + b2s;
            }
        }
    } else {
        // ---- General fallback (rare): full clamped two-segment form ----
#pragma unroll
        for (int t = 0; t < 2; ++t) {
            int s0g = s_base + t * 4;
            float accs[4];
            for (int j = 0; j < 4; ++j) {
                accs[j] = 0.f;
                int sample = s0g + j;
                if (sample >= total) continue;
                int b1 = (b1shift >= 0) ? (sample >> b1shift)
                                        : (int)((unsigned)sample / (unsigned)b2n);
                float a = 0.f;
                for (int rr = 0; rr < NUM_R; ++rr) {
                    float2 g = sg[wid][t][j][rr];
                    int m0 = __float2int_rn(g.y * 16384.0f);
                    float vy = g_vy[b1][rr];
                    int ka = max(min(-16384 - m0, KLEN), 0);
                    int kb = max(min(-m0,          KLEN), 0);
                    int kd = max(min(16384 - m0,   KLEN), 0);
                    float m0f = (float)m0;
                    if (kb > ka) {
                        float pa = g_P[rr][kb][0][lane] - g_P[rr][ka][0][lane];
                        float pb = g_P[rr][kb][1][lane] - g_P[rr][ka][1][lane];
                        a += vy * (fmaf(m0f, inv, 1.0f) * pa + inv * pb);
                    }
                    if (kd > kb) {
                        float pa = g_P[rr][kd][0][lane] - g_P[rr][kb][0][lane];
                        float pb = g_P[rr][kd][1][lane] - g_P[rr][kb][1][lane];
                        a += vy * (fmaf(-m0f, inv, 1.0f) * pa - inv * pb);
                    }
                }
                accs[j] = a;
            }
            float c0 = fmaxf(accs[0] + blane, 0.f) * wlane;
            float c1 = fmaxf(accs[1] + blane, 0.f) * wlane;
            float c2 = fmaxf(accs[2] + blane, 0.f) * wlane;
            float c3 = fmaxf(accs[3] + blane, 0.f) * wlane;

            float t0 = __shfl_xor_sync(0xffffffffu, c0, 16);
            float t1 = __shfl_xor_sync(0xffffffffu, c1, 16);
            float t2 = __shfl_xor_sync(0xffffffffu, c2, 16);
            float t3 = __shfl_xor_sync(0xffffffffu, c3, 16);
            bool lo16 = lane < 16;
            float v = lo16 ? (c0 + t0) : (c1 + t1);
            float w = lo16 ? (c2 + t2) : (c3 + t3);
            float tv = __shfl_xor_sync(0xffffffffu, v, 8);
            float tw = __shfl_xor_sync(0xffffffffu, w, 8);
            float z = ((lane & 8) == 0) ? (v + tv) : (w + tw);
            z += __shfl_xor_sync(0xffffffffu, z, 4);
            z += __shfl_xor_sync(0xffffffffu, z, 2);
            z += __shfl_xor_sync(0xffffffffu, z, 1);

            if ((lane & 7) == 0) {
                int g = ((lane >> 2) & 2) | (lane >> 4);
                int idx = s0g + g;
                if (idx < total) out[idx] = z + b2s;
            }
        }
    }
}

extern "C" void kernel_launch(void* const* d_in, const int* in_sizes, int n_in,
                              void* d_out, int out_size) {
    const float* rec  = (const float*)d_in[0];
    const float* sloc = (const float*)d_in[1];
    const float* emit = (const float*)d_in[2];
    const float* rloc = (const float*)d_in[3];
    const float* W1   = (const float*)d_in[4];
    const float* b1v  = (const float*)d_in[5];
    const float* W2   = (const float*)d_in[6];
    const float* b2v  = (const float*)d_in[7];
    float* out = (float*)d_out;

    int nb1 = in_sizes[0] / (NUM_R * LREC);       // B1
    if (nb1 < 1) nb1 = 1;
    if (nb1 > MAXB1) nb1 = MAXB1;
    int total = out_size;                         // B1*B2 samples
    int b2n = total / nb1;

    int b1shift = -1;
    if (b2n > 0 && (b2n & (b2n - 1)) == 0) {
        b1shift = 0;
        while ((1 << b1shift) != b2n) ++b1shift;
    }

    prep_kernel<<<NUM_R * nb1, 256>>>(W1, rec);

    int blocks = (total + 63) / 64;               // 64 samples per block

    // PDL launch: tof's geometry overlaps prep; fallback to plain launch.
    cudaLaunchConfig_t cfg = {};
    cfg.gridDim  = dim3((unsigned)blocks, 1, 1);
    cfg.blockDim = dim3(256, 1, 1);
    cfg.dynamicSmemBytes = 0;
    cfg.stream = 0;
    cudaLaunchAttribute at[1];
    at[0].id = cudaLaunchAttributeProgrammaticStreamSerialization;
    at[0].val.programmaticStreamSerializationAllowed = 1;
    cfg.attrs = at;
    cfg.numAttrs = 1;
    cudaError_t e = cudaLaunchKernelEx(&cfg, tof_kernel,
                                       sloc, emit, rloc, b1v, W2, b2v, out,
                                       total, b2n, b1shift);
    if (e != cudaSuccess) {
        (void)cudaGetLastError();   // clear sticky error
        tof_kernel<<<blocks, 256>>>(sloc, emit, rloc, b1v, W2, b2v, out,
                                    total, b2n, b1shift);
    }
}